// round 9
// baseline (speedup 1.0000x reference)
#include <cuda_runtime.h>
#include <math.h>
#include <stdint.h>
#include <stddef.h>

// ---------------------------------------------------------------------------
// LagunaMoE R7: mma.sync tf32 GEMM, pre-rounded operands, vector B loads
// (tcgen05 unavailable: harness compiles via compute_103 virtual arch)
// T=2048, H=2048, E=16, K=4, I=1408, IS=5632, scale=2.5, softcap=30
// ---------------------------------------------------------------------------

#define T_TOK 2048
#define HID   2048
#define NEXP  16
#define TOPK  4
#define IDIM  1408
#define ISH   5632

// -------------------- device scratch (static, allocation-free) -------------
__device__ float g_sgu  [(size_t)T_TOK * (2 * ISH)];
__device__ float g_sact [(size_t)T_TOK * ISH];
__device__ float g_sdown[(size_t)T_TOK * HID];
__device__ float g_rgu  [(size_t)T_TOK * TOPK * (2 * IDIM)];
__device__ float g_ract [(size_t)T_TOK * TOPK * IDIM];
__device__ float g_rdown[(size_t)T_TOK * TOPK * HID];

__device__ float g_xr   [(size_t)T_TOK * HID];             // tf32-rounded x
__device__ float g_wgu_t[(size_t)NEXP * 2 * IDIM * HID];   // [E][2I][H] T+perm
__device__ float g_wdn_t[(size_t)NEXP * HID * IDIM];       // [E][H][I]  T+perm
__device__ float g_sguT [(size_t)2 * ISH * HID];           // [2IS][H]   T+perm
__device__ float g_sdnT [(size_t)HID * ISH];               // [H][IS]    T+perm

__device__ int   g_topk_ids[T_TOK * TOPK];
__device__ float g_topk_w  [T_TOK * TOPK];
__device__ int   g_counts[NEXP];
__device__ int   g_offs  [NEXP + 1];
__device__ int   g_cursor[NEXP];
__device__ int   g_perm  [T_TOK * TOPK];
__device__ int   g_rowof [T_TOK * TOPK];

// -------------------- PTX helpers ------------------------------------------
__device__ __forceinline__ uint32_t f2tf(float f) {
    uint32_t u;
    asm("cvt.rna.tf32.f32 %0, %1;" : "=r"(u) : "f"(f));
    return u;
}
__device__ __forceinline__ void mma_tf32(float* c, const uint32_t* a,
                                         uint32_t b0, uint32_t b1) {
    asm volatile(
        "mma.sync.aligned.m16n8k8.row.col.f32.tf32.tf32.f32 "
        "{%0,%1,%2,%3}, {%4,%5,%6,%7}, {%8,%9}, {%0,%1,%2,%3};"
        : "+f"(c[0]), "+f"(c[1]), "+f"(c[2]), "+f"(c[3])
        : "r"(a[0]), "r"(a[1]), "r"(a[2]), "r"(a[3]), "r"(b0), "r"(b1));
}
__device__ __forceinline__ void cp16(uint32_t dst, const void* src) {
    asm volatile("cp.async.cg.shared.global [%0], [%1], 16;\n" :: "r"(dst), "l"(src));
}
__device__ __forceinline__ void cp_commit() { asm volatile("cp.async.commit_group;\n"); }
__device__ __forceinline__ void cp_wait0()  { asm volatile("cp.async.wait_group 0;\n"); }
__device__ __forceinline__ void cp_wait1()  { asm volatile("cp.async.wait_group 1;\n"); }

// -------------------- small kernels ----------------------------------------
__global__ void zero_counts_kernel() {
    if (threadIdx.x < NEXP) g_counts[threadIdx.x] = 0;
}

__global__ __launch_bounds__(256) void router_kernel(
    const float* __restrict__ x, const float* __restrict__ gw,
    const float* __restrict__ bias)
{
    const int t = blockIdx.x;
    const float* xr = x + (size_t)t * HID;

    float acc[NEXP];
#pragma unroll
    for (int e = 0; e < NEXP; e++) acc[e] = 0.f;
    for (int h = threadIdx.x; h < HID; h += 256) {
        const float xv = xr[h];
#pragma unroll
        for (int e = 0; e < NEXP; e++)
            acc[e] = fmaf(xv, gw[e * HID + h], acc[e]);
    }
#pragma unroll
    for (int e = 0; e < NEXP; e++) {
        float v = acc[e];
#pragma unroll
        for (int off = 16; off > 0; off >>= 1)
            v += __shfl_xor_sync(0xffffffffu, v, off);
        acc[e] = v;
    }
    __shared__ float red[NEXP][8];
    __shared__ float s_score[NEXP], s_sel[NEXP];
    const int warp = threadIdx.x >> 5, lane = threadIdx.x & 31;
    if (lane == 0) {
#pragma unroll
        for (int e = 0; e < NEXP; e++) red[e][warp] = acc[e];
    }
    __syncthreads();
    if (threadIdx.x < NEXP) {
        float v = 0.f;
#pragma unroll
        for (int w = 0; w < 8; w++) v += red[threadIdx.x][w];
        v = tanhf(v * (1.0f / 30.0f)) * 30.0f;
        const float sc = 1.0f / (1.0f + expf(-v));
        s_score[threadIdx.x] = sc;
        s_sel[threadIdx.x]   = sc + bias[threadIdx.x];
    }
    __syncthreads();
    if (threadIdx.x == 0) {
        int ids[TOPK]; float ws[TOPK]; float wsum = 0.f;
        unsigned used = 0;
        for (int k = 0; k < TOPK; k++) {
            int best = 0; float bv = -1e30f;
            for (int e = 0; e < NEXP; e++)
                if (!((used >> e) & 1u) && s_sel[e] > bv) { bv = s_sel[e]; best = e; }
            used |= (1u << best);
            ids[k] = best; ws[k] = s_score[best]; wsum += s_score[best];
        }
        const float inv = 1.0f / wsum;
        for (int k = 0; k < TOPK; k++) {
            g_topk_ids[t * TOPK + k] = ids[k];
            g_topk_w  [t * TOPK + k] = ws[k] * inv;
            atomicAdd(&g_counts[ids[k]], 1);
        }
    }
}

__global__ void scan_kernel() {
    if (threadIdx.x == 0) {
        int s = 0;
        for (int e = 0; e < NEXP; e++) { g_offs[e] = s; s += g_counts[e]; g_cursor[e] = 0; }
        g_offs[NEXP] = s;
    }
}

__global__ void build_perm_kernel() {
    const int t = blockIdx.x * blockDim.x + threadIdx.x;
    if (t >= T_TOK) return;
    for (int k = 0; k < TOPK; k++) {
        const int e = g_topk_ids[t * TOPK + k];
        const int pos = g_offs[e] + atomicAdd(&g_cursor[e], 1);
        g_perm[pos] = t;
        g_rowof[t * TOPK + k] = pos;
    }
}

// Round x to tf32 (rna) into g_xr
__global__ void round_x_kernel(const float* __restrict__ x) {
    const int i = blockIdx.x * 256 + threadIdx.x;
    g_xr[i] = __uint_as_float(f2tf(x[i]));
}

// Transpose [R, C] -> [C, R] with tf32 rounding and k-interleave within each
// 16-block of the output row: k -> (k&~15) | ((k&3)*4 + ((k>>2)&3)).
// (R is the GEMM K dim and must be a multiple of 16 — holds for 2048/1408/5632.)
__global__ __launch_bounds__(256) void transpose_rna_kernel(
    const float* __restrict__ in, float* __restrict__ out,
    int R, int C, size_t inStride, size_t outStride)
{
    in  += (size_t)blockIdx.z * inStride;
    out += (size_t)blockIdx.z * outStride;
    __shared__ float tile[32][33];
    const int c0 = blockIdx.x * 32, r0 = blockIdx.y * 32;
    const int tx = threadIdx.x, ty = threadIdx.y;   // block (32, 8)
#pragma unroll
    for (int i = ty; i < 32; i += 8)
        tile[i][tx] = in[(size_t)(r0 + i) * C + c0 + tx];
    __syncthreads();
#pragma unroll
    for (int i = ty; i < 32; i += 8) {
        const int rr = r0 + tx;
        const int rp = (rr & ~15) | (((rr & 3) << 2) | ((rr >> 2) & 3));
        out[(size_t)(c0 + i) * R + rp] = __uint_as_float(f2tf(tile[tx][i]));
    }
}

// -------------------- tf32 mma.sync GEMM, 128x128 tile, 4 warps ------------
// C[M,N] = A[M,K] @ Bt[N,K]^T
//   A: natural [m][k], tf32-pre-rounded
//   Bt: pre-transposed [n][k], tf32-pre-rounded, k-interleaved per 16-block
// MODE 0: plain; MODE 1: grouped by expert (blockIdx.z);
// MODE 2: grouped + A-row indirection through g_perm.
// 3-stage cp.async pipeline. Dyn smem: 3 * (A 128x20f + B 128x16f) = 55296 B.
#define STAGE_FLOATS 4608          // 18432 B per stage
#define A_FLOATS     2560          // 128 rows * 20 (padded)
#define GEMM_SMEM_BYTES (3 * 18432)

template <int MODE>
__global__ __launch_bounds__(128, 2) void gemm_mma_kernel(
    const float* __restrict__ A, int K,
    const float* __restrict__ Bt, size_t btstride,
    float* __restrict__ C, int ldc, int M)
{
    int rowOff = 0, Mloc = M;
    const float* Bp = Bt;
    if (MODE >= 1) {
        const int e = blockIdx.z;
        rowOff = g_offs[e];
        Mloc = g_offs[e + 1] - rowOff;
        Bp += (size_t)e * btstride;
    }
    const int m0 = blockIdx.y * 128;
    if (m0 >= Mloc) return;
    const int n0 = blockIdx.x * 128;

    extern __shared__ float sm[];

    const int tid = threadIdx.x;
    const int l   = tid & 31;
    const int wid = tid >> 5;          // 0..3
    const int mw  = (wid & 1) * 64;    // warp m offset
    const int nw  = (wid >> 1) * 64;   // warp n offset

    // ---- staging pointers (thread t owns A row t and B row t, 4 chunks each)
    const int rA  = m0 + tid;
    const int rCl = (rA < Mloc) ? rA : (Mloc - 1);
    const float* aRowPtr;
    if (MODE == 2)      aRowPtr = A + (size_t)g_perm[rowOff + rCl] * K;
    else if (MODE == 1) aRowPtr = A + (size_t)(rowOff + rCl) * K;
    else                aRowPtr = A + (size_t)rCl * K;
    const float* bRowPtr = Bp + (size_t)(n0 + tid) * K;

    const uint32_t smem_base = (uint32_t)__cvta_generic_to_shared(sm);
    const uint32_t aDst = smem_base + (uint32_t)tid * 80;            // row*20 floats
    const uint32_t bDst = smem_base + A_FLOATS * 4 + (uint32_t)tid * 64;

    float acc[4][8][4];
#pragma unroll
    for (int i = 0; i < 4; i++)
#pragma unroll
        for (int j = 0; j < 8; j++)
#pragma unroll
            for (int q = 0; q < 4; q++) acc[i][j][q] = 0.f;

    const int S = K >> 4;   // 16-wide K stages

    auto stage = [&](int buf, int slab) {
        const uint32_t so = (uint32_t)buf * (STAGE_FLOATS * 4);
        const float* ga = aRowPtr + (size_t)slab * 16;
#pragma unroll
        for (int c = 0; c < 4; c++) cp16(aDst + so + c * 16, ga + c * 4);
        const float* gb = bRowPtr + (size_t)slab * 16;
#pragma unroll
        for (int c = 0; c < 4; c++) cp16(bDst + so + c * 16, gb + c * 4);
        cp_commit();
    };

    stage(0, 0);
    if (S > 1) stage(1, 1);

    const int lmRow = l & 15;
    const int lmCol = (l & 16) ? 4 : 0;
    const int bRow  = (l >> 2);      // n within 8-block
    const int bCol  = (l & 3) << 2;  // interleaved k group

    for (int kt = 0; kt < S; ++kt) {
        if (kt == S - 1) cp_wait0(); else cp_wait1();
        __syncthreads();
        const int buf = kt % 3;
        if (kt + 2 < S) stage((kt + 2) % 3, kt + 2);

        const float* AsBuf = sm + buf * STAGE_FLOATS;            // stride 20
        const float* BsBuf = sm + buf * STAGE_FLOATS + A_FLOATS; // stride 16

        // B fragments: one LDS.128 per 8-wide n block covers both k8 steps
        float4 bfrag[8];
#pragma unroll
        for (int j = 0; j < 8; j++)
            bfrag[j] = *(const float4*)(BsBuf + (nw + 8 * j + bRow) * 16 + bCol);

#pragma unroll
        for (int ks = 0; ks < 2; ks++) {
            uint32_t a[4][4];
#pragma unroll
            for (int i = 0; i < 4; i++) {
                uint32_t addr = (uint32_t)__cvta_generic_to_shared(
                    AsBuf + (mw + 16 * i + lmRow) * 20 + ks * 8 + lmCol);
                asm volatile(
                    "ldmatrix.sync.aligned.m8n8.x4.shared.b16 {%0,%1,%2,%3}, [%4];"
                    : "=r"(a[i][0]), "=r"(a[i][1]), "=r"(a[i][2]), "=r"(a[i][3])
                    : "r"(addr));
            }
#pragma unroll
            for (int i = 0; i < 4; i++)
#pragma unroll
                for (int j = 0; j < 8; j++) {
                    const uint32_t b0 = __float_as_uint(ks ? bfrag[j].z : bfrag[j].x);
                    const uint32_t b1 = __float_as_uint(ks ? bfrag[j].w : bfrag[j].y);
                    mma_tf32(acc[i][j], a[i], b0, b1);
                }
        }
        __syncthreads();
    }

    // ---- epilogue ----
#pragma unroll
    for (int i = 0; i < 4; i++) {
        const int r0 = m0 + mw + 16 * i + (l >> 2);
        const int r1 = r0 + 8;
        const int colb = n0 + nw + 2 * (l & 3);
        if (r0 < Mloc) {
            float* cp = C + (size_t)(rowOff + r0) * ldc + colb;
#pragma unroll
            for (int j = 0; j < 8; j++)
                *(float2*)(cp + 8 * j) = make_float2(acc[i][j][0], acc[i][j][1]);
        }
        if (r1 < Mloc) {
            float* cp = C + (size_t)(rowOff + r1) * ldc + colb;
#pragma unroll
            for (int j = 0; j < 8; j++)
                *(float2*)(cp + 8 * j) = make_float2(acc[i][j][2], acc[i][j][3]);
        }
    }
}

// -------------------- elementwise -----------------------------------------
// SwiGLU; output tf32-rounded (feeds next GEMM's A operand)
__global__ void swiglu_kernel(const float* __restrict__ gu, float* __restrict__ act,
                              int icols, int nTotal)
{
    const int idx = blockIdx.x * 256 + threadIdx.x;
    if (idx >= nTotal) return;
    const int r = idx / icols;
    const int c = idx - r * icols;
    const size_t base = (size_t)r * (2 * icols);
    const float g = gu[base + c];
    const float u = gu[base + icols + c];
    const float v = (g / (1.0f + expf(-g))) * u;
    act[idx] = __uint_as_float(f2tf(v));
}

__global__ void combine_kernel(float* __restrict__ out, const float* __restrict__ sdown)
{
    const int idx = blockIdx.x * 256 + threadIdx.x;
    const int t = idx >> 11;
    const int h = idx & (HID - 1);
    float r = 0.f;
#pragma unroll
    for (int k = 0; k < TOPK; k++) {
        const int pos = g_rowof[t * TOPK + k];
        r = fmaf(g_topk_w[t * TOPK + k], g_rdown[(size_t)pos * HID + h], r);
    }
    out[idx] = fmaf(2.5f, r, sdown[idx]);
}

// -------------------- launch -----------------------------------------------
extern "C" void kernel_launch(void* const* d_in, const int* in_sizes, int n_in,
                              void* d_out, int out_size)
{
    const float* x    = (const float*)d_in[0];   // [T, H]
    const float* gw   = (const float*)d_in[1];   // [E, H]
    const float* cb   = (const float*)d_in[2];   // [E]
    const float* wgu  = (const float*)d_in[3];   // [E, H, 2I]
    const float* wdn  = (const float*)d_in[4];   // [E, I, H]
    const float* swgu = (const float*)d_in[5];   // [H, 2*IS]
    const float* swdn = (const float*)d_in[6];   // [IS, H]
    float* out = (float*)d_out;
    (void)in_sizes; (void)n_in; (void)out_size;

    float *p_sgu, *p_sact, *p_sdown, *p_rgu, *p_ract, *p_rdown;
    float *p_xr, *p_wguT, *p_wdnT, *p_sguT, *p_sdnT;
    cudaGetSymbolAddress((void**)&p_sgu,   g_sgu);
    cudaGetSymbolAddress((void**)&p_sact,  g_sact);
    cudaGetSymbolAddress((void**)&p_sdown, g_sdown);
    cudaGetSymbolAddress((void**)&p_rgu,   g_rgu);
    cudaGetSymbolAddress((void**)&p_ract,  g_ract);
    cudaGetSymbolAddress((void**)&p_rdown, g_rdown);
    cudaGetSymbolAddress((void**)&p_xr,    g_xr);
    cudaGetSymbolAddress((void**)&p_wguT,  g_wgu_t);
    cudaGetSymbolAddress((void**)&p_wdnT,  g_wdn_t);
    cudaGetSymbolAddress((void**)&p_sguT,  g_sguT);
    cudaGetSymbolAddress((void**)&p_sdnT,  g_sdnT);

    cudaFuncSetAttribute(gemm_mma_kernel<0>,
        cudaFuncAttributeMaxDynamicSharedMemorySize, GEMM_SMEM_BYTES);
    cudaFuncSetAttribute(gemm_mma_kernel<1>,
        cudaFuncAttributeMaxDynamicSharedMemorySize, GEMM_SMEM_BYTES);
    cudaFuncSetAttribute(gemm_mma_kernel<2>,
        cudaFuncAttributeMaxDynamicSharedMemorySize, GEMM_SMEM_BYTES);

    // ---- routing ----
    zero_counts_kernel<<<1, 32>>>();
    router_kernel<<<T_TOK, 256>>>(x, gw, cb);
    scan_kernel<<<1, 32>>>();
    build_perm_kernel<<<(T_TOK + 255) / 256, 256>>>();

    // ---- precondition: round x; transpose+round+interleave weights ----
    round_x_kernel<<<(T_TOK * HID) / 256, 256>>>(x);
    transpose_rna_kernel<<<dim3(2 * IDIM / 32, HID / 32, NEXP), dim3(32, 8)>>>(
        wgu, p_wguT, HID, 2 * IDIM, (size_t)HID * 2 * IDIM, (size_t)HID * 2 * IDIM);
    transpose_rna_kernel<<<dim3(HID / 32, IDIM / 32, NEXP), dim3(32, 8)>>>(
        wdn, p_wdnT, IDIM, HID, (size_t)IDIM * HID, (size_t)IDIM * HID);
    transpose_rna_kernel<<<dim3(2 * ISH / 32, HID / 32, 1), dim3(32, 8)>>>(
        swgu, p_sguT, HID, 2 * ISH, 0, 0);
    transpose_rna_kernel<<<dim3(HID / 32, ISH / 32, 1), dim3(32, 8)>>>(
        swdn, p_sdnT, ISH, HID, 0, 0);

    // ---- routed experts (grouped, tf32 mma.sync) ----
    gemm_mma_kernel<2><<<dim3(2 * IDIM / 128, 16, NEXP), 128, GEMM_SMEM_BYTES>>>(
        p_xr, HID, p_wguT, (size_t)2 * IDIM * HID, p_rgu, 2 * IDIM, 0);
    swiglu_kernel<<<(T_TOK * TOPK * IDIM + 255) / 256, 256>>>(
        p_rgu, p_ract, IDIM, T_TOK * TOPK * IDIM);
    gemm_mma_kernel<1><<<dim3(HID / 128, 16, NEXP), 128, GEMM_SMEM_BYTES>>>(
        p_ract, IDIM, p_wdnT, (size_t)HID * IDIM, p_rdown, HID, 0);

    // ---- shared expert (tf32 mma.sync) ----
    gemm_mma_kernel<0><<<dim3(2 * ISH / 128, T_TOK / 128, 1), 128, GEMM_SMEM_BYTES>>>(
        p_xr, HID, p_sguT, 0, p_sgu, 2 * ISH, T_TOK);
    swiglu_kernel<<<(T_TOK * ISH + 255) / 256, 256>>>(
        p_sgu, p_sact, ISH, T_TOK * ISH);
    gemm_mma_kernel<0><<<dim3(HID / 128, T_TOK / 128, 1), 128, GEMM_SMEM_BYTES>>>(
        p_sact, ISH, p_sdnT, 0, p_sdown, HID, T_TOK);

    // ---- combine: out = 2.5 * routed + shared ----
    combine_kernel<<<(T_TOK * HID) / 256, 256>>>(out, p_sdown);
}

// round 10
// speedup vs baseline: 1.2676x; 1.2676x over previous
#include <cuda_runtime.h>
#include <math.h>
#include <stdint.h>
#include <stddef.h>

// ---------------------------------------------------------------------------
// LagunaMoE R9: tf32 mma.sync GEMM, 256 thr / 8 warps (R4 occupancy) +
// pre-rounded operands & vector B loads (R7 lean loop).
// T=2048, H=2048, E=16, K=4, I=1408, IS=5632, scale=2.5, softcap=30
// ---------------------------------------------------------------------------

#define T_TOK 2048
#define HID   2048
#define NEXP  16
#define TOPK  4
#define IDIM  1408
#define ISH   5632

// -------------------- device scratch (static, allocation-free) -------------
__device__ float g_sgu  [(size_t)T_TOK * (2 * ISH)];
__device__ float g_sact [(size_t)T_TOK * ISH];
__device__ float g_sdown[(size_t)T_TOK * HID];
__device__ float g_rgu  [(size_t)T_TOK * TOPK * (2 * IDIM)];
__device__ float g_ract [(size_t)T_TOK * TOPK * IDIM];
__device__ float g_rdown[(size_t)T_TOK * TOPK * HID];

__device__ float g_xr   [(size_t)T_TOK * HID];             // tf32-rounded x
__device__ float g_wgu_t[(size_t)NEXP * 2 * IDIM * HID];   // [E][2I][H] T+perm
__device__ float g_wdn_t[(size_t)NEXP * HID * IDIM];       // [E][H][I]  T+perm
__device__ float g_sguT [(size_t)2 * ISH * HID];           // [2IS][H]   T+perm
__device__ float g_sdnT [(size_t)HID * ISH];               // [H][IS]    T+perm

__device__ int   g_topk_ids[T_TOK * TOPK];
__device__ float g_topk_w  [T_TOK * TOPK];
__device__ int   g_counts[NEXP];
__device__ int   g_offs  [NEXP + 1];
__device__ int   g_cursor[NEXP];
__device__ int   g_perm  [T_TOK * TOPK];
__device__ int   g_rowof [T_TOK * TOPK];

// -------------------- PTX helpers ------------------------------------------
__device__ __forceinline__ uint32_t f2tf(float f) {
    uint32_t u;
    asm("cvt.rna.tf32.f32 %0, %1;" : "=r"(u) : "f"(f));
    return u;
}
__device__ __forceinline__ void mma_tf32(float* c, const uint32_t* a,
                                         uint32_t b0, uint32_t b1) {
    asm volatile(
        "mma.sync.aligned.m16n8k8.row.col.f32.tf32.tf32.f32 "
        "{%0,%1,%2,%3}, {%4,%5,%6,%7}, {%8,%9}, {%0,%1,%2,%3};"
        : "+f"(c[0]), "+f"(c[1]), "+f"(c[2]), "+f"(c[3])
        : "r"(a[0]), "r"(a[1]), "r"(a[2]), "r"(a[3]), "r"(b0), "r"(b1));
}
__device__ __forceinline__ void cp16(uint32_t dst, const void* src) {
    asm volatile("cp.async.cg.shared.global [%0], [%1], 16;\n" :: "r"(dst), "l"(src));
}
__device__ __forceinline__ void cp_commit() { asm volatile("cp.async.commit_group;\n"); }
__device__ __forceinline__ void cp_wait0()  { asm volatile("cp.async.wait_group 0;\n"); }
__device__ __forceinline__ void cp_wait1()  { asm volatile("cp.async.wait_group 1;\n"); }

// -------------------- small kernels ----------------------------------------
__global__ void zero_counts_kernel() {
    if (threadIdx.x < NEXP) g_counts[threadIdx.x] = 0;
}

__global__ __launch_bounds__(256) void router_kernel(
    const float* __restrict__ x, const float* __restrict__ gw,
    const float* __restrict__ bias)
{
    const int t = blockIdx.x;
    const float* xr = x + (size_t)t * HID;

    float acc[NEXP];
#pragma unroll
    for (int e = 0; e < NEXP; e++) acc[e] = 0.f;
    for (int h = threadIdx.x; h < HID; h += 256) {
        const float xv = xr[h];
#pragma unroll
        for (int e = 0; e < NEXP; e++)
            acc[e] = fmaf(xv, gw[e * HID + h], acc[e]);
    }
#pragma unroll
    for (int e = 0; e < NEXP; e++) {
        float v = acc[e];
#pragma unroll
        for (int off = 16; off > 0; off >>= 1)
            v += __shfl_xor_sync(0xffffffffu, v, off);
        acc[e] = v;
    }
    __shared__ float red[NEXP][8];
    __shared__ float s_score[NEXP], s_sel[NEXP];
    const int warp = threadIdx.x >> 5, lane = threadIdx.x & 31;
    if (lane == 0) {
#pragma unroll
        for (int e = 0; e < NEXP; e++) red[e][warp] = acc[e];
    }
    __syncthreads();
    if (threadIdx.x < NEXP) {
        float v = 0.f;
#pragma unroll
        for (int w = 0; w < 8; w++) v += red[threadIdx.x][w];
        v = tanhf(v * (1.0f / 30.0f)) * 30.0f;
        const float sc = 1.0f / (1.0f + expf(-v));
        s_score[threadIdx.x] = sc;
        s_sel[threadIdx.x]   = sc + bias[threadIdx.x];
    }
    __syncthreads();
    if (threadIdx.x == 0) {
        int ids[TOPK]; float ws[TOPK]; float wsum = 0.f;
        unsigned used = 0;
        for (int k = 0; k < TOPK; k++) {
            int best = 0; float bv = -1e30f;
            for (int e = 0; e < NEXP; e++)
                if (!((used >> e) & 1u) && s_sel[e] > bv) { bv = s_sel[e]; best = e; }
            used |= (1u << best);
            ids[k] = best; ws[k] = s_score[best]; wsum += s_score[best];
        }
        const float inv = 1.0f / wsum;
        for (int k = 0; k < TOPK; k++) {
            g_topk_ids[t * TOPK + k] = ids[k];
            g_topk_w  [t * TOPK + k] = ws[k] * inv;
            atomicAdd(&g_counts[ids[k]], 1);
        }
    }
}

__global__ void scan_kernel() {
    if (threadIdx.x == 0) {
        int s = 0;
        for (int e = 0; e < NEXP; e++) { g_offs[e] = s; s += g_counts[e]; g_cursor[e] = 0; }
        g_offs[NEXP] = s;
    }
}

__global__ void build_perm_kernel() {
    const int t = blockIdx.x * blockDim.x + threadIdx.x;
    if (t >= T_TOK) return;
    for (int k = 0; k < TOPK; k++) {
        const int e = g_topk_ids[t * TOPK + k];
        const int pos = g_offs[e] + atomicAdd(&g_cursor[e], 1);
        g_perm[pos] = t;
        g_rowof[t * TOPK + k] = pos;
    }
}

// Round x to tf32 (rna) into g_xr
__global__ void round_x_kernel(const float* __restrict__ x) {
    const int i = blockIdx.x * 256 + threadIdx.x;
    g_xr[i] = __uint_as_float(f2tf(x[i]));
}

// Transpose [R, C] -> [C, R] with tf32 rounding and k-interleave within each
// 16-block of the output row: k -> (k&~15) | ((k&3)*4 + ((k>>2)&3)).
__global__ __launch_bounds__(256) void transpose_rna_kernel(
    const float* __restrict__ in, float* __restrict__ out,
    int R, int C, size_t inStride, size_t outStride)
{
    in  += (size_t)blockIdx.z * inStride;
    out += (size_t)blockIdx.z * outStride;
    __shared__ float tile[32][33];
    const int c0 = blockIdx.x * 32, r0 = blockIdx.y * 32;
    const int tx = threadIdx.x, ty = threadIdx.y;   // block (32, 8)
#pragma unroll
    for (int i = ty; i < 32; i += 8)
        tile[i][tx] = in[(size_t)(r0 + i) * C + c0 + tx];
    __syncthreads();
#pragma unroll
    for (int i = ty; i < 32; i += 8) {
        const int rr = r0 + tx;
        const int rp = (rr & ~15) | (((rr & 3) << 2) | ((rr >> 2) & 3));
        out[(size_t)(c0 + i) * R + rp] = __uint_as_float(f2tf(tile[tx][i]));
    }
}

// -------------------- tf32 mma.sync GEMM, 128x128 tile, 8 warps ------------
// C[M,N] = A[M,K] @ Bt[N,K]^T
//   A: natural [m][k], tf32-pre-rounded
//   Bt: pre-transposed [n][k], tf32-pre-rounded, k-interleaved per 16-block
// Warp grid 4x2 (mw = (w&3)*32, nw = (w>>2)*64), warp tile 32x64.
// 3-stage cp.async pipeline. Dyn smem: 3 * (128*20 + 128*16) * 4 = 55296 B.
#define STAGE_FLOATS 4608          // floats per stage
#define A_FLOATS     2560          // 128 rows * 20 (padded)
#define GEMM_SMEM_BYTES (3 * 18432)

template <int MODE>
__global__ __launch_bounds__(256, 2) void gemm_mma_kernel(
    const float* __restrict__ A, int K,
    const float* __restrict__ Bt, size_t btstride,
    float* __restrict__ C, int ldc, int M)
{
    int rowOff = 0, Mloc = M;
    const float* Bp = Bt;
    if (MODE >= 1) {
        const int e = blockIdx.z;
        rowOff = g_offs[e];
        Mloc = g_offs[e + 1] - rowOff;
        Bp += (size_t)e * btstride;
    }
    const int m0 = blockIdx.y * 128;
    if (m0 >= Mloc) return;
    const int n0 = blockIdx.x * 128;

    extern __shared__ float sm[];

    const int tid = threadIdx.x;
    const int l   = tid & 31;
    const int wid = tid >> 5;          // 0..7
    const int mw  = (wid & 3) * 32;    // warp m offset
    const int nw  = (wid >> 2) * 64;   // warp n offset

    // ---- staging: thread pair per row (128 A rows + 128 B rows, 16 floats ea)
    const int sRow  = tid >> 1;          // 0..127
    const int sHalf = tid & 1;           // 0/1 -> 8-float half
    const int rA  = m0 + sRow;
    const int rCl = (rA < Mloc) ? rA : (Mloc - 1);
    const float* aRowPtr;
    if (MODE == 2)      aRowPtr = A + (size_t)g_perm[rowOff + rCl] * K;
    else if (MODE == 1) aRowPtr = A + (size_t)(rowOff + rCl) * K;
    else                aRowPtr = A + (size_t)rCl * K;
    aRowPtr += sHalf * 8;
    const float* bRowPtr = Bp + (size_t)(n0 + sRow) * K + sHalf * 8;

    const uint32_t smem_base = (uint32_t)__cvta_generic_to_shared(sm);
    const uint32_t aDst = smem_base + (uint32_t)(sRow * 20 + sHalf * 8) * 4;
    const uint32_t bDst = smem_base + A_FLOATS * 4 + (uint32_t)(sRow * 16 + sHalf * 8) * 4;

    float acc[2][8][4];
#pragma unroll
    for (int i = 0; i < 2; i++)
#pragma unroll
        for (int j = 0; j < 8; j++)
#pragma unroll
            for (int q = 0; q < 4; q++) acc[i][j][q] = 0.f;

    const int S = K >> 4;   // 16-wide K stages

    auto stage = [&](int buf, int slab) {
        const uint32_t so = (uint32_t)buf * (STAGE_FLOATS * 4);
        const float* ga = aRowPtr + (size_t)slab * 16;
        cp16(aDst + so,      ga);
        cp16(aDst + so + 16, ga + 4);
        const float* gb = bRowPtr + (size_t)slab * 16;
        cp16(bDst + so,      gb);
        cp16(bDst + so + 16, gb + 4);
        cp_commit();
    };

    stage(0, 0);
    if (S > 1) stage(1, 1);

    const int lmRow = l & 15;
    const int lmCol = (l & 16) ? 4 : 0;
    const int bRow  = (l >> 2);      // n within 8-block
    const int bCol  = (l & 3) << 2;  // interleaved k group

    for (int kt = 0; kt < S; ++kt) {
        if (kt == S - 1) cp_wait0(); else cp_wait1();
        __syncthreads();
        const int buf = kt % 3;
        if (kt + 2 < S) stage((kt + 2) % 3, kt + 2);

        const float* AsBuf = sm + buf * STAGE_FLOATS;            // stride 20
        const float* BsBuf = sm + buf * STAGE_FLOATS + A_FLOATS; // stride 16

        // B fragments: one LDS.128 per 8-wide n block covers both k8 steps
        float4 bfrag[8];
#pragma unroll
        for (int j = 0; j < 8; j++)
            bfrag[j] = *(const float4*)(BsBuf + (nw + 8 * j + bRow) * 16 + bCol);

#pragma unroll
        for (int ks = 0; ks < 2; ks++) {
            uint32_t a[2][4];
#pragma unroll
            for (int i = 0; i < 2; i++) {
                uint32_t addr = (uint32_t)__cvta_generic_to_shared(
                    AsBuf + (mw + 16 * i + lmRow) * 20 + ks * 8 + lmCol);
                asm volatile(
                    "ldmatrix.sync.aligned.m8n8.x4.shared.b16 {%0,%1,%2,%3}, [%4];"
                    : "=r"(a[i][0]), "=r"(a[i][1]), "=r"(a[i][2]), "=r"(a[i][3])
                    : "r"(addr));
            }
#pragma unroll
            for (int i = 0; i < 2; i++)
#pragma unroll
                for (int j = 0; j < 8; j++) {
                    const uint32_t b0 = __float_as_uint(ks ? bfrag[j].z : bfrag[j].x);
                    const uint32_t b1 = __float_as_uint(ks ? bfrag[j].w : bfrag[j].y);
                    mma_tf32(acc[i][j], a[i], b0, b1);
                }
        }
        __syncthreads();
    }

    // ---- epilogue ----
#pragma unroll
    for (int i = 0; i < 2; i++) {
        const int r0 = m0 + mw + 16 * i + (l >> 2);
        const int r1 = r0 + 8;
        const int colb = n0 + nw + 2 * (l & 3);
        if (r0 < Mloc) {
            float* cp = C + (size_t)(rowOff + r0) * ldc + colb;
#pragma unroll
            for (int j = 0; j < 8; j++)
                *(float2*)(cp + 8 * j) = make_float2(acc[i][j][0], acc[i][j][1]);
        }
        if (r1 < Mloc) {
            float* cp = C + (size_t)(rowOff + r1) * ldc + colb;
#pragma unroll
            for (int j = 0; j < 8; j++)
                *(float2*)(cp + 8 * j) = make_float2(acc[i][j][2], acc[i][j][3]);
        }
    }
}

// -------------------- elementwise -----------------------------------------
// SwiGLU; output tf32-rounded (feeds next GEMM's A operand)
__global__ void swiglu_kernel(const float* __restrict__ gu, float* __restrict__ act,
                              int icols, int nTotal)
{
    const int idx = blockIdx.x * 256 + threadIdx.x;
    if (idx >= nTotal) return;
    const int r = idx / icols;
    const int c = idx - r * icols;
    const size_t base = (size_t)r * (2 * icols);
    const float g = gu[base + c];
    const float u = gu[base + icols + c];
    const float v = (g / (1.0f + expf(-g))) * u;
    act[idx] = __uint_as_float(f2tf(v));
}

__global__ void combine_kernel(float* __restrict__ out, const float* __restrict__ sdown)
{
    const int idx = blockIdx.x * 256 + threadIdx.x;
    const int t = idx >> 11;
    const int h = idx & (HID - 1);
    float r = 0.f;
#pragma unroll
    for (int k = 0; k < TOPK; k++) {
        const int pos = g_rowof[t * TOPK + k];
        r = fmaf(g_topk_w[t * TOPK + k], g_rdown[(size_t)pos * HID + h], r);
    }
    out[idx] = fmaf(2.5f, r, sdown[idx]);
}

// -------------------- launch -----------------------------------------------
extern "C" void kernel_launch(void* const* d_in, const int* in_sizes, int n_in,
                              void* d_out, int out_size)
{
    const float* x    = (const float*)d_in[0];   // [T, H]
    const float* gw   = (const float*)d_in[1];   // [E, H]
    const float* cb   = (const float*)d_in[2];   // [E]
    const float* wgu  = (const float*)d_in[3];   // [E, H, 2I]
    const float* wdn  = (const float*)d_in[4];   // [E, I, H]
    const float* swgu = (const float*)d_in[5];   // [H, 2*IS]
    const float* swdn = (const float*)d_in[6];   // [IS, H]
    float* out = (float*)d_out;
    (void)in_sizes; (void)n_in; (void)out_size;

    float *p_sgu, *p_sact, *p_sdown, *p_rgu, *p_ract, *p_rdown;
    float *p_xr, *p_wguT, *p_wdnT, *p_sguT, *p_sdnT;
    cudaGetSymbolAddress((void**)&p_sgu,   g_sgu);
    cudaGetSymbolAddress((void**)&p_sact,  g_sact);
    cudaGetSymbolAddress((void**)&p_sdown, g_sdown);
    cudaGetSymbolAddress((void**)&p_rgu,   g_rgu);
    cudaGetSymbolAddress((void**)&p_ract,  g_ract);
    cudaGetSymbolAddress((void**)&p_rdown, g_rdown);
    cudaGetSymbolAddress((void**)&p_xr,    g_xr);
    cudaGetSymbolAddress((void**)&p_wguT,  g_wgu_t);
    cudaGetSymbolAddress((void**)&p_wdnT,  g_wdn_t);
    cudaGetSymbolAddress((void**)&p_sguT,  g_sguT);
    cudaGetSymbolAddress((void**)&p_sdnT,  g_sdnT);

    cudaFuncSetAttribute(gemm_mma_kernel<0>,
        cudaFuncAttributeMaxDynamicSharedMemorySize, GEMM_SMEM_BYTES);
    cudaFuncSetAttribute(gemm_mma_kernel<1>,
        cudaFuncAttributeMaxDynamicSharedMemorySize, GEMM_SMEM_BYTES);
    cudaFuncSetAttribute(gemm_mma_kernel<2>,
        cudaFuncAttributeMaxDynamicSharedMemorySize, GEMM_SMEM_BYTES);

    // ---- routing ----
    zero_counts_kernel<<<1, 32>>>();
    router_kernel<<<T_TOK, 256>>>(x, gw, cb);
    scan_kernel<<<1, 32>>>();
    build_perm_kernel<<<(T_TOK + 255) / 256, 256>>>();

    // ---- precondition: round x; transpose+round+interleave weights ----
    round_x_kernel<<<(T_TOK * HID) / 256, 256>>>(x);
    transpose_rna_kernel<<<dim3(2 * IDIM / 32, HID / 32, NEXP), dim3(32, 8)>>>(
        wgu, p_wguT, HID, 2 * IDIM, (size_t)HID * 2 * IDIM, (size_t)HID * 2 * IDIM);
    transpose_rna_kernel<<<dim3(HID / 32, IDIM / 32, NEXP), dim3(32, 8)>>>(
        wdn, p_wdnT, IDIM, HID, (size_t)IDIM * HID, (size_t)IDIM * HID);
    transpose_rna_kernel<<<dim3(2 * ISH / 32, HID / 32, 1), dim3(32, 8)>>>(
        swgu, p_sguT, HID, 2 * ISH, 0, 0);
    transpose_rna_kernel<<<dim3(HID / 32, ISH / 32, 1), dim3(32, 8)>>>(
        swdn, p_sdnT, ISH, HID, 0, 0);

    // ---- routed experts (grouped, tf32 mma.sync) ----
    gemm_mma_kernel<2><<<dim3(2 * IDIM / 128, 16, NEXP), 256, GEMM_SMEM_BYTES>>>(
        p_xr, HID, p_wguT, (size_t)2 * IDIM * HID, p_rgu, 2 * IDIM, 0);
    swiglu_kernel<<<(T_TOK * TOPK * IDIM + 255) / 256, 256>>>(
        p_rgu, p_ract, IDIM, T_TOK * TOPK * IDIM);
    gemm_mma_kernel<1><<<dim3(HID / 128, 16, NEXP), 256, GEMM_SMEM_BYTES>>>(
        p_ract, IDIM, p_wdnT, (size_t)HID * IDIM, p_rdown, HID, 0);

    // ---- shared expert (tf32 mma.sync) ----
    gemm_mma_kernel<0><<<dim3(2 * ISH / 128, T_TOK / 128, 1), 256, GEMM_SMEM_BYTES>>>(
        p_xr, HID, p_sguT, 0, p_sgu, 2 * ISH, T_TOK);
    swiglu_kernel<<<(T_TOK * ISH + 255) / 256, 256>>>(
        p_sgu, p_sact, ISH, T_TOK * ISH);
    gemm_mma_kernel<0><<<dim3(HID / 128, T_TOK / 128, 1), 256, GEMM_SMEM_BYTES>>>(
        p_sact, ISH, p_sdnT, 0, p_sdown, HID, T_TOK);

    // ---- combine: out = 2.5 * routed + shared ----
    combine_kernel<<<(T_TOK * HID) / 256, 256>>>(out, p_sdown);
}

// round 11
// speedup vs baseline: 2.0946x; 1.6524x over previous
#include <cuda_runtime.h>
#include <cuda_fp16.h>
#include <math.h>
#include <stdint.h>
#include <stddef.h>

// ---------------------------------------------------------------------------
// LagunaMoE R10: fp16 mma.sync m16n8k16 GEMM (same 10-bit mantissa as tf32,
// 2x MACs per HMMA). 256 thr / 8 warps, 3-stage cp.async, half operands.
// T=2048, H=2048, E=16, K=4, I=1408, IS=5632, scale=2.5, softcap=30
// ---------------------------------------------------------------------------

#define T_TOK 2048
#define HID   2048
#define NEXP  16
#define TOPK  4
#define IDIM  1408
#define ISH   5632

// -------------------- device scratch (static, allocation-free) -------------
__device__ float  g_sgu  [(size_t)T_TOK * (2 * ISH)];        // shared gate_up out (f32)
__device__ __half g_sact [(size_t)T_TOK * ISH];              // shared act (half)
__device__ float  g_sdown[(size_t)T_TOK * HID];              // shared down out
__device__ float  g_rgu  [(size_t)T_TOK * TOPK * (2 * IDIM)];
__device__ __half g_ract [(size_t)T_TOK * TOPK * IDIM];
__device__ float  g_rdown[(size_t)T_TOK * TOPK * HID];

__device__ __half g_xh   [(size_t)T_TOK * HID];              // fp16 x
__device__ __half g_wgu_t[(size_t)NEXP * 2 * IDIM * HID];    // [E][2I][H]
__device__ __half g_wdn_t[(size_t)NEXP * HID * IDIM];        // [E][H][I]
__device__ __half g_sguT [(size_t)2 * ISH * HID];            // [2IS][H]
__device__ __half g_sdnT [(size_t)HID * ISH];                // [H][IS]

__device__ int   g_topk_ids[T_TOK * TOPK];
__device__ float g_topk_w  [T_TOK * TOPK];
__device__ int   g_counts[NEXP];
__device__ int   g_offs  [NEXP + 1];
__device__ int   g_cursor[NEXP];
__device__ int   g_perm  [T_TOK * TOPK];
__device__ int   g_rowof [T_TOK * TOPK];

// -------------------- PTX helpers ------------------------------------------
__device__ __forceinline__ void mma_f16(float* c, const uint32_t* a,
                                        uint32_t b0, uint32_t b1) {
    asm volatile(
        "mma.sync.aligned.m16n8k16.row.col.f32.f16.f16.f32 "
        "{%0,%1,%2,%3}, {%4,%5,%6,%7}, {%8,%9}, {%0,%1,%2,%3};"
        : "+f"(c[0]), "+f"(c[1]), "+f"(c[2]), "+f"(c[3])
        : "r"(a[0]), "r"(a[1]), "r"(a[2]), "r"(a[3]), "r"(b0), "r"(b1));
}
__device__ __forceinline__ void cp16(uint32_t dst, const void* src) {
    asm volatile("cp.async.cg.shared.global [%0], [%1], 16;\n" :: "r"(dst), "l"(src));
}
__device__ __forceinline__ void cp_commit() { asm volatile("cp.async.commit_group;\n"); }
__device__ __forceinline__ void cp_wait0()  { asm volatile("cp.async.wait_group 0;\n"); }
__device__ __forceinline__ void cp_wait1()  { asm volatile("cp.async.wait_group 1;\n"); }

// -------------------- small kernels ----------------------------------------
__global__ void zero_counts_kernel() {
    if (threadIdx.x < NEXP) g_counts[threadIdx.x] = 0;
}

__global__ __launch_bounds__(256) void router_kernel(
    const float* __restrict__ x, const float* __restrict__ gw,
    const float* __restrict__ bias)
{
    const int t = blockIdx.x;
    const float* xr = x + (size_t)t * HID;

    float acc[NEXP];
#pragma unroll
    for (int e = 0; e < NEXP; e++) acc[e] = 0.f;
    for (int h = threadIdx.x; h < HID; h += 256) {
        const float xv = xr[h];
#pragma unroll
        for (int e = 0; e < NEXP; e++)
            acc[e] = fmaf(xv, gw[e * HID + h], acc[e]);
    }
#pragma unroll
    for (int e = 0; e < NEXP; e++) {
        float v = acc[e];
#pragma unroll
        for (int off = 16; off > 0; off >>= 1)
            v += __shfl_xor_sync(0xffffffffu, v, off);
        acc[e] = v;
    }
    __shared__ float red[NEXP][8];
    __shared__ float s_score[NEXP], s_sel[NEXP];
    const int warp = threadIdx.x >> 5, lane = threadIdx.x & 31;
    if (lane == 0) {
#pragma unroll
        for (int e = 0; e < NEXP; e++) red[e][warp] = acc[e];
    }
    __syncthreads();
    if (threadIdx.x < NEXP) {
        float v = 0.f;
#pragma unroll
        for (int w = 0; w < 8; w++) v += red[threadIdx.x][w];
        v = tanhf(v * (1.0f / 30.0f)) * 30.0f;
        const float sc = 1.0f / (1.0f + expf(-v));
        s_score[threadIdx.x] = sc;
        s_sel[threadIdx.x]   = sc + bias[threadIdx.x];
    }
    __syncthreads();
    if (threadIdx.x == 0) {
        int ids[TOPK]; float ws[TOPK]; float wsum = 0.f;
        unsigned used = 0;
        for (int k = 0; k < TOPK; k++) {
            int best = 0; float bv = -1e30f;
            for (int e = 0; e < NEXP; e++)
                if (!((used >> e) & 1u) && s_sel[e] > bv) { bv = s_sel[e]; best = e; }
            used |= (1u << best);
            ids[k] = best; ws[k] = s_score[best]; wsum += s_score[best];
        }
        const float inv = 1.0f / wsum;
        for (int k = 0; k < TOPK; k++) {
            g_topk_ids[t * TOPK + k] = ids[k];
            g_topk_w  [t * TOPK + k] = ws[k] * inv;
            atomicAdd(&g_counts[ids[k]], 1);
        }
    }
}

__global__ void scan_kernel() {
    if (threadIdx.x == 0) {
        int s = 0;
        for (int e = 0; e < NEXP; e++) { g_offs[e] = s; s += g_counts[e]; g_cursor[e] = 0; }
        g_offs[NEXP] = s;
    }
}

__global__ void build_perm_kernel() {
    const int t = blockIdx.x * blockDim.x + threadIdx.x;
    if (t >= T_TOK) return;
    for (int k = 0; k < TOPK; k++) {
        const int e = g_topk_ids[t * TOPK + k];
        const int pos = g_offs[e] + atomicAdd(&g_cursor[e], 1);
        g_perm[pos] = t;
        g_rowof[t * TOPK + k] = pos;
    }
}

// Convert x to fp16
__global__ void cvt_x_kernel(const float* __restrict__ x) {
    const int i = blockIdx.x * 256 + threadIdx.x;
    g_xh[i] = __float2half_rn(x[i]);
}

// Transpose [R, C] f32 -> [C, R] fp16 (32x32 smem tiles)
__global__ __launch_bounds__(256) void transpose_h_kernel(
    const float* __restrict__ in, __half* __restrict__ out,
    int R, int C, size_t inStride, size_t outStride)
{
    in  += (size_t)blockIdx.z * inStride;
    out += (size_t)blockIdx.z * outStride;
    __shared__ float tile[32][33];
    const int c0 = blockIdx.x * 32, r0 = blockIdx.y * 32;
    const int tx = threadIdx.x, ty = threadIdx.y;   // block (32, 8)
#pragma unroll
    for (int i = ty; i < 32; i += 8)
        tile[i][tx] = in[(size_t)(r0 + i) * C + c0 + tx];
    __syncthreads();
#pragma unroll
    for (int i = ty; i < 32; i += 8)
        out[(size_t)(c0 + i) * R + r0 + tx] = __float2half_rn(tile[tx][i]);
}

// -------------------- fp16 mma.sync GEMM, 128x128 tile, 8 warps ------------
// C[M,N] = A[M,K] @ Bt[N,K]^T   (A, Bt fp16; C f32)
// Warp grid 4x2 (mw=(w&3)*32, nw=(w>>2)*64), warp tile 32x64, BK=16.
// smem rows: 16 halfs of data, stride 24 halfs (48 B: 16B-aligned rows,
// ldmatrix start banks 12i mod 32 all-distinct => conflict-free).
// 3-stage pipeline: 3 * (128 + 128 rows) * 48 B = 36864 B.
#define ROW_HALFS   24
#define A_HALFS     (128 * ROW_HALFS)          // 3072
#define STAGE_HALFS (2 * A_HALFS)              // 6144
#define STAGE_BYTES (STAGE_HALFS * 2)          // 12288
#define GEMM_SMEM_BYTES (3 * STAGE_BYTES)      // 36864

template <int MODE>
__global__ __launch_bounds__(256, 2) void gemm_mma_kernel(
    const __half* __restrict__ A, int K,
    const __half* __restrict__ Bt, size_t btstride,
    float* __restrict__ C, int ldc, int M)
{
    int rowOff = 0, Mloc = M;
    const __half* Bp = Bt;
    if (MODE >= 1) {
        const int e = blockIdx.z;
        rowOff = g_offs[e];
        Mloc = g_offs[e + 1] - rowOff;
        Bp += (size_t)e * btstride;
    }
    const int m0 = blockIdx.y * 128;
    if (m0 >= Mloc) return;
    const int n0 = blockIdx.x * 128;

    extern __shared__ __half smh[];

    const int tid = threadIdx.x;
    const int l   = tid & 31;
    const int wid = tid >> 5;          // 0..7
    const int mw  = (wid & 3) * 32;    // warp m offset
    const int nw  = (wid >> 2) * 64;   // warp n offset

    // ---- staging: 2 threads per row; 16B chunk each (8 halfs) ----
    const int sRow  = tid >> 1;          // 0..127
    const int sHalf = tid & 1;           // k chunk 0/1
    const int rA  = m0 + sRow;
    const int rCl = (rA < Mloc) ? rA : (Mloc - 1);
    const __half* aRowPtr;
    if (MODE == 2)      aRowPtr = A + (size_t)g_perm[rowOff + rCl] * K;
    else if (MODE == 1) aRowPtr = A + (size_t)(rowOff + rCl) * K;
    else                aRowPtr = A + (size_t)rCl * K;
    aRowPtr += sHalf * 8;
    const __half* bRowPtr = Bp + (size_t)(n0 + sRow) * K + sHalf * 8;

    const uint32_t smem_base = (uint32_t)__cvta_generic_to_shared(smh);
    const uint32_t aDst = smem_base + (uint32_t)(sRow * ROW_HALFS + sHalf * 8) * 2;
    const uint32_t bDst = aDst + A_HALFS * 2;

    float acc[2][8][4];
#pragma unroll
    for (int i = 0; i < 2; i++)
#pragma unroll
        for (int j = 0; j < 8; j++)
#pragma unroll
            for (int q = 0; q < 4; q++) acc[i][j][q] = 0.f;

    const int S = K >> 4;   // K16 stages

    auto stage = [&](int buf, int slab) {
        const uint32_t so = (uint32_t)buf * STAGE_BYTES;
        cp16(aDst + so, aRowPtr + (size_t)slab * 16);
        cp16(bDst + so, bRowPtr + (size_t)slab * 16);
        cp_commit();
    };

    stage(0, 0);
    if (S > 1) stage(1, 1);

    // ldmatrix lane->address maps
    const int aRowSel = l & 15;               // A: row within 16-block
    const int aKoff   = (l & 16) ? 8 : 0;     // A: k chunk
    const int bRowSel = (l & 7) + ((l & 16) ? 8 : 0);  // B: n within 16-block
    const int bKoff   = (l & 8) ? 8 : 0;      // B: k chunk

    for (int kt = 0; kt < S; ++kt) {
        if (kt == S - 1) cp_wait0(); else cp_wait1();
        __syncthreads();
        const int buf = kt % 3;
        if (kt + 2 < S) stage((kt + 2) % 3, kt + 2);

        const __half* AsBuf = smh + buf * STAGE_HALFS;
        const __half* BsBuf = AsBuf + A_HALFS;

        // B fragments: 4 ldmatrix.x4, each covers 2 n-octets x k16
        uint32_t bfr[4][4];
#pragma unroll
        for (int j = 0; j < 4; j++) {
            uint32_t addr = (uint32_t)__cvta_generic_to_shared(
                BsBuf + (nw + 16 * j + bRowSel) * ROW_HALFS + bKoff);
            asm volatile(
                "ldmatrix.sync.aligned.m8n8.x4.shared.b16 {%0,%1,%2,%3}, [%4];"
                : "=r"(bfr[j][0]), "=r"(bfr[j][1]), "=r"(bfr[j][2]), "=r"(bfr[j][3])
                : "r"(addr));
        }
        // A fragments: 2 ldmatrix.x4 (two 16-row m blocks)
        uint32_t a[2][4];
#pragma unroll
        for (int i = 0; i < 2; i++) {
            uint32_t addr = (uint32_t)__cvta_generic_to_shared(
                AsBuf + (mw + 16 * i + aRowSel) * ROW_HALFS + aKoff);
            asm volatile(
                "ldmatrix.sync.aligned.m8n8.x4.shared.b16 {%0,%1,%2,%3}, [%4];"
                : "=r"(a[i][0]), "=r"(a[i][1]), "=r"(a[i][2]), "=r"(a[i][3])
                : "r"(addr));
        }
#pragma unroll
        for (int i = 0; i < 2; i++)
#pragma unroll
            for (int j = 0; j < 4; j++) {
                mma_f16(acc[i][2 * j],     a[i], bfr[j][0], bfr[j][1]);
                mma_f16(acc[i][2 * j + 1], a[i], bfr[j][2], bfr[j][3]);
            }
        __syncthreads();
    }

    // ---- epilogue ----
#pragma unroll
    for (int i = 0; i < 2; i++) {
        const int r0 = m0 + mw + 16 * i + (l >> 2);
        const int r1 = r0 + 8;
        const int colb = n0 + nw + 2 * (l & 3);
        if (r0 < Mloc) {
            float* cp = C + (size_t)(rowOff + r0) * ldc + colb;
#pragma unroll
            for (int j = 0; j < 8; j++)
                *(float2*)(cp + 8 * j) = make_float2(acc[i][j][0], acc[i][j][1]);
        }
        if (r1 < Mloc) {
            float* cp = C + (size_t)(rowOff + r1) * ldc + colb;
#pragma unroll
            for (int j = 0; j < 8; j++)
                *(float2*)(cp + 8 * j) = make_float2(acc[i][j][2], acc[i][j][3]);
        }
    }
}

// -------------------- elementwise -----------------------------------------
// SwiGLU; output fp16 (feeds next GEMM's A operand)
__global__ void swiglu_kernel(const float* __restrict__ gu, __half* __restrict__ act,
                              int icols, int nTotal)
{
    const int idx = blockIdx.x * 256 + threadIdx.x;
    if (idx >= nTotal) return;
    const int r = idx / icols;
    const int c = idx - r * icols;
    const size_t base = (size_t)r * (2 * icols);
    const float g = gu[base + c];
    const float u = gu[base + icols + c];
    const float v = (g / (1.0f + expf(-g))) * u;
    act[idx] = __float2half_rn(v);
}

__global__ void combine_kernel(float* __restrict__ out, const float* __restrict__ sdown)
{
    const int idx = blockIdx.x * 256 + threadIdx.x;
    const int t = idx >> 11;
    const int h = idx & (HID - 1);
    float r = 0.f;
#pragma unroll
    for (int k = 0; k < TOPK; k++) {
        const int pos = g_rowof[t * TOPK + k];
        r = fmaf(g_topk_w[t * TOPK + k], g_rdown[(size_t)pos * HID + h], r);
    }
    out[idx] = fmaf(2.5f, r, sdown[idx]);
}

// -------------------- launch -----------------------------------------------
extern "C" void kernel_launch(void* const* d_in, const int* in_sizes, int n_in,
                              void* d_out, int out_size)
{
    const float* x    = (const float*)d_in[0];   // [T, H]
    const float* gw   = (const float*)d_in[1];   // [E, H]
    const float* cb   = (const float*)d_in[2];   // [E]
    const float* wgu  = (const float*)d_in[3];   // [E, H, 2I]
    const float* wdn  = (const float*)d_in[4];   // [E, I, H]
    const float* swgu = (const float*)d_in[5];   // [H, 2*IS]
    const float* swdn = (const float*)d_in[6];   // [IS, H]
    float* out = (float*)d_out;
    (void)in_sizes; (void)n_in; (void)out_size;

    float  *p_sgu, *p_sdown, *p_rgu, *p_rdown;
    __half *p_sact, *p_ract, *p_xh, *p_wguT, *p_wdnT, *p_sguT, *p_sdnT;
    cudaGetSymbolAddress((void**)&p_sgu,   g_sgu);
    cudaGetSymbolAddress((void**)&p_sact,  g_sact);
    cudaGetSymbolAddress((void**)&p_sdown, g_sdown);
    cudaGetSymbolAddress((void**)&p_rgu,   g_rgu);
    cudaGetSymbolAddress((void**)&p_ract,  g_ract);
    cudaGetSymbolAddress((void**)&p_rdown, g_rdown);
    cudaGetSymbolAddress((void**)&p_xh,    g_xh);
    cudaGetSymbolAddress((void**)&p_wguT,  g_wgu_t);
    cudaGetSymbolAddress((void**)&p_wdnT,  g_wdn_t);
    cudaGetSymbolAddress((void**)&p_sguT,  g_sguT);
    cudaGetSymbolAddress((void**)&p_sdnT,  g_sdnT);

    cudaFuncSetAttribute(gemm_mma_kernel<0>,
        cudaFuncAttributeMaxDynamicSharedMemorySize, GEMM_SMEM_BYTES);
    cudaFuncSetAttribute(gemm_mma_kernel<1>,
        cudaFuncAttributeMaxDynamicSharedMemorySize, GEMM_SMEM_BYTES);
    cudaFuncSetAttribute(gemm_mma_kernel<2>,
        cudaFuncAttributeMaxDynamicSharedMemorySize, GEMM_SMEM_BYTES);

    // ---- routing ----
    zero_counts_kernel<<<1, 32>>>();
    router_kernel<<<T_TOK, 256>>>(x, gw, cb);
    scan_kernel<<<1, 32>>>();
    build_perm_kernel<<<(T_TOK + 255) / 256, 256>>>();

    // ---- precondition: x -> fp16; weights transpose -> fp16 ----
    cvt_x_kernel<<<(T_TOK * HID) / 256, 256>>>(x);
    transpose_h_kernel<<<dim3(2 * IDIM / 32, HID / 32, NEXP), dim3(32, 8)>>>(
        wgu, p_wguT, HID, 2 * IDIM, (size_t)HID * 2 * IDIM, (size_t)HID * 2 * IDIM);
    transpose_h_kernel<<<dim3(HID / 32, IDIM / 32, NEXP), dim3(32, 8)>>>(
        wdn, p_wdnT, IDIM, HID, (size_t)IDIM * HID, (size_t)IDIM * HID);
    transpose_h_kernel<<<dim3(2 * ISH / 32, HID / 32, 1), dim3(32, 8)>>>(
        swgu, p_sguT, HID, 2 * ISH, 0, 0);
    transpose_h_kernel<<<dim3(HID / 32, ISH / 32, 1), dim3(32, 8)>>>(
        swdn, p_sdnT, ISH, HID, 0, 0);

    // ---- routed experts (grouped, fp16 mma) ----
    gemm_mma_kernel<2><<<dim3(2 * IDIM / 128, 16, NEXP), 256, GEMM_SMEM_BYTES>>>(
        p_xh, HID, p_wguT, (size_t)2 * IDIM * HID, p_rgu, 2 * IDIM, 0);
    swiglu_kernel<<<(T_TOK * TOPK * IDIM + 255) / 256, 256>>>(
        p_rgu, p_ract, IDIM, T_TOK * TOPK * IDIM);
    gemm_mma_kernel<1><<<dim3(HID / 128, 16, NEXP), 256, GEMM_SMEM_BYTES>>>(
        p_ract, IDIM, p_wdnT, (size_t)HID * IDIM, p_rdown, HID, 0);

    // ---- shared expert (fp16 mma) ----
    gemm_mma_kernel<0><<<dim3(2 * ISH / 128, T_TOK / 128, 1), 256, GEMM_SMEM_BYTES>>>(
        p_xh, HID, p_sguT, 0, p_sgu, 2 * ISH, T_TOK);
    swiglu_kernel<<<(T_TOK * ISH + 255) / 256, 256>>>(
        p_sgu, p_sact, ISH, T_TOK * ISH);
    gemm_mma_kernel<0><<<dim3(HID / 128, T_TOK / 128, 1), 256, GEMM_SMEM_BYTES>>>(
        p_sact, ISH, p_sdnT, 0, p_sdown, HID, T_TOK);

    // ---- combine: out = 2.5 * routed + shared ----
    combine_kernel<<<(T_TOK * HID) / 256, 256>>>(out, p_sdown);
}